// round 10
// baseline (speedup 1.0000x reference)
#include <cuda_runtime.h>
#include <cstdint>

// SNN: x[B,5] -> L1(32) -> spike(dot>=2) -> L2(32) -> L3(16) -> L4(10) -> spike.
// Neuron-per-lane: lane j owns W1 row j (5 regs, loaded once). x staged
// transposed with padded pitch (conflict-light STS, LDS.128 broadcast reads:
// 5 loads per 4 rows). mask1 = ballot. Gate (popc >= g_minpop, sound bound,
// rel_err==0 R3-R9) batched over 16 rows -> one rare branch per 16 rows.

__device__ int g_minpop;

__global__ void setup_kernel(const float* __restrict__ W2) {
    int i = threadIdx.x;
    float mx = W2[i];
    #pragma unroll
    for (int j = 1; j < 32; j++) mx = fmaxf(mx, W2[j * 32 + i]);
    #pragma unroll
    for (int s = 16; s > 0; s >>= 1)
        mx = fmaxf(mx, __shfl_xor_sync(0xffffffffu, mx, s));
    if (i == 0) {
        int mp = 1;  // smallest popc whose bound popc*cmax could round to >= 2
        while (mp < 33 && (float)mp * mx < 1.99f) mp++;
        g_minpop = mp;
    }
}

// Warp-parallel exact layers 2-4 (lane j = neuron j); validated in R6.
__device__ __noinline__ void rare_warp(unsigned m1, float* __restrict__ orow,
                                       int lane,
                                       const float* __restrict__ W2,
                                       const float* __restrict__ W3,
                                       const float* __restrict__ W4)
{
    float a2 = 0.0f;
    unsigned mm = m1;
    while (mm) { int i = __ffs(mm) - 1; mm &= mm - 1; a2 += W2[lane * 32 + i]; }
    unsigned m2 = __ballot_sync(0xffffffffu, a2 >= 2.0f);
    if (!m2) return;

    const int l3 = (lane < 16) ? lane : 0;
    float a3 = 0.0f;
    mm = m2;
    while (mm) { int i = __ffs(mm) - 1; mm &= mm - 1; a3 += W3[l3 * 32 + i]; }
    unsigned m3 = __ballot_sync(0xffffffffu, (lane < 16) && (a3 >= 2.0f));
    if (!m3) return;

    const int l4 = (lane < 10) ? lane : 0;
    float a4 = 0.0f;
    mm = m3;
    while (mm) { int i = __ffs(mm) - 1; mm &= mm - 1; a4 += W4[l4 * 16 + i]; }
    if (lane < 10) orow[lane] = (a4 >= 2.0f) ? 1.0f : 0.0f;
}

#define BT    256
#define RPB   512
#define RPW   64          // rows per warp
#define PITCH 520         // padded row pitch for sXT (cuts STS conflicts)

__global__ __launch_bounds__(BT)
void snn_kernel(const float* __restrict__ x,
                const float* __restrict__ W1,
                const float* __restrict__ W2,
                const float* __restrict__ W3,
                const float* __restrict__ W4,
                float* __restrict__ out)
{
    __shared__ float sXT[5][PITCH];   // x transposed, padded

    const int tid  = threadIdx.x;
    const int lane = tid & 31;
    const int wid  = tid >> 5;
    const size_t rowbase = (size_t)blockIdx.x * RPB;
    const int mp = g_minpop;

    // lane j's neuron weights, once per block (L2-resident after block 0)
    const float w0 = __ldg(&W1[lane * 5 + 0]);
    const float w1 = __ldg(&W1[lane * 5 + 1]);
    const float w2 = __ldg(&W1[lane * 5 + 2]);
    const float w3 = __ldg(&W1[lane * 5 + 3]);
    const float w4 = __ldg(&W1[lane * 5 + 4]);

    // stage x transposed (coalesced LDG.128; STS scatter over padded pitch)
    {
        const float4* xv = reinterpret_cast<const float4*>(x + rowbase * 5);
        #pragma unroll
        for (int i = tid; i < RPB * 5 / 4; i += BT) {
            float4 v = xv[i];
            int e = 4 * i;
            sXT[e % 5][e / 5] = v.x;
            sXT[(e + 1) % 5][(e + 1) / 5] = v.y;
            sXT[(e + 2) % 5][(e + 2) / 5] = v.z;
            sXT[(e + 3) % 5][(e + 3) / 5] = v.w;
        }
    }
    // zero-fill output tile (coalesced STG.128); rare writes after the sync
    // overwrite nonzero rows (pattern validated R3-R9).
    {
        float4* ov = reinterpret_cast<float4*>(out + rowbase * 10);
        const float4 z = make_float4(0.f, 0.f, 0.f, 0.f);
        #pragma unroll
        for (int i = tid; i < RPB * 10 / 4; i += BT) ov[i] = z;
    }
    __syncthreads();

    const int rbeg = wid * RPW;

    for (int it = 0; it < RPW / 16; ++it) {     // 4 iterations of 16 rows
        const int r16 = rbeg + it * 16;
        unsigned m[16];
        unsigned gate = 0;

        #pragma unroll
        for (int g = 0; g < 4; ++g) {           // 4 rows per sub-group
            const int r = r16 + g * 4;
            float d0, d1, d2, d3;
            {
                float4 t = *reinterpret_cast<const float4*>(&sXT[0][r]);
                d0 = w0 * t.x; d1 = w0 * t.y; d2 = w0 * t.z; d3 = w0 * t.w;
            }
            {
                float4 t = *reinterpret_cast<const float4*>(&sXT[1][r]);
                d0 = fmaf(w1, t.x, d0); d1 = fmaf(w1, t.y, d1);
                d2 = fmaf(w1, t.z, d2); d3 = fmaf(w1, t.w, d3);
            }
            {
                float4 t = *reinterpret_cast<const float4*>(&sXT[2][r]);
                d0 = fmaf(w2, t.x, d0); d1 = fmaf(w2, t.y, d1);
                d2 = fmaf(w2, t.z, d2); d3 = fmaf(w2, t.w, d3);
            }
            {
                float4 t = *reinterpret_cast<const float4*>(&sXT[3][r]);
                d0 = fmaf(w3, t.x, d0); d1 = fmaf(w3, t.y, d1);
                d2 = fmaf(w3, t.z, d2); d3 = fmaf(w3, t.w, d3);
            }
            {
                float4 t = *reinterpret_cast<const float4*>(&sXT[4][r]);
                d0 = fmaf(w4, t.x, d0); d1 = fmaf(w4, t.y, d1);
                d2 = fmaf(w4, t.z, d2); d3 = fmaf(w4, t.w, d3);
            }
            m[4 * g + 0] = __ballot_sync(0xffffffffu, d0 >= 2.0f);
            m[4 * g + 1] = __ballot_sync(0xffffffffu, d1 >= 2.0f);
            m[4 * g + 2] = __ballot_sync(0xffffffffu, d2 >= 2.0f);
            m[4 * g + 3] = __ballot_sync(0xffffffffu, d3 >= 2.0f);
            gate |= (unsigned)(__popc(m[4 * g + 0]) >= mp) << (4 * g + 0);
            gate |= (unsigned)(__popc(m[4 * g + 1]) >= mp) << (4 * g + 1);
            gate |= (unsigned)(__popc(m[4 * g + 2]) >= mp) << (4 * g + 2);
            gate |= (unsigned)(__popc(m[4 * g + 3]) >= mp) << (4 * g + 3);
        }

        if (gate) {                              // warp-uniform, ~1e-3 taken
            float* ob = out + (rowbase + r16) * 10;
            #pragma unroll
            for (int q = 0; q < 16; ++q)
                if ((gate >> q) & 1u)
                    rare_warp(m[q], ob + q * 10, lane, W2, W3, W4);
        }
    }
}

extern "C" void kernel_launch(void* const* d_in, const int* in_sizes, int n_in,
                              void* d_out, int out_size)
{
    const float* x  = (const float*)d_in[0];
    const float* W1 = (const float*)d_in[1];
    const float* W2 = (const float*)d_in[2];
    const float* W3 = (const float*)d_in[3];
    const float* W4 = (const float*)d_in[4];
    float* out = (float*)d_out;

    const int B = in_sizes[0] / 5;        // 2097152
    const int grid = B / RPB;             // 4096

    setup_kernel<<<1, 32>>>(W2);
    snn_kernel<<<grid, BT>>>(x, W1, W2, W3, W4, out);
}

// round 11
// speedup vs baseline: 1.3747x; 1.3747x over previous
#include <cuda_runtime.h>
#include <cstdint>

// SNN: x[B,5] -> L1(32) -> spike(dot>=2) -> L2(32) -> L3(16) -> L4(10) -> spike.
// Single kernel (minpop computed inline per block by warp 0). W1 in
// __constant__ (scalar LDC, best measured variant R8). x staged through
// shared (coalesced LDG.128 + conflict-free LDS.32). Zero-fill + rare
// scatter output; popc gate (sound bound, rel_err==0 across R3-R10).

__constant__ __align__(16) float cW1[160];

// exact layers 2-4 (rare, ~1e-4 of rows); identical to R1-R10 validated code.
__device__ __noinline__ unsigned rare_path(unsigned mask1,
                                           const float* __restrict__ W2,
                                           const float* __restrict__ W3,
                                           const float* __restrict__ W4)
{
    unsigned mask2 = 0;
    #pragma unroll
    for (int jc = 0; jc < 32; jc += 8) {
        float acc[8] = {0, 0, 0, 0, 0, 0, 0, 0};
        unsigned mm = mask1;
        while (mm) {
            int i = __ffs(mm) - 1; mm &= mm - 1;
            #pragma unroll
            for (int j = 0; j < 8; j++) acc[j] += W2[(jc + j) * 32 + i];
        }
        #pragma unroll
        for (int j = 0; j < 8; j++)
            if (acc[j] >= 2.0f) mask2 |= 1u << (jc + j);
    }
    if (!mask2) return 0;

    unsigned mask3 = 0;
    #pragma unroll
    for (int jc = 0; jc < 16; jc += 8) {
        float acc[8] = {0, 0, 0, 0, 0, 0, 0, 0};
        unsigned mm = mask2;
        while (mm) {
            int i = __ffs(mm) - 1; mm &= mm - 1;
            #pragma unroll
            for (int j = 0; j < 8; j++) acc[j] += W3[(jc + j) * 32 + i];
        }
        #pragma unroll
        for (int j = 0; j < 8; j++)
            if (acc[j] >= 2.0f) mask3 |= 1u << (jc + j);
    }
    if (!mask3) return 0;

    float acc4[10];
    #pragma unroll
    for (int j = 0; j < 10; j++) acc4[j] = 0.0f;
    unsigned mm = mask3;
    while (mm) {
        int i = __ffs(mm) - 1; mm &= mm - 1;
        #pragma unroll
        for (int j = 0; j < 10; j++) acc4[j] += W4[j * 16 + i];
    }
    unsigned om = 0;
    #pragma unroll
    for (int j = 0; j < 10; j++)
        if (acc4[j] >= 2.0f) om |= 1u << j;
    return om;
}

#define BT 256

__global__ __launch_bounds__(BT)
void snn_kernel(const float* __restrict__ x,
                const float* __restrict__ W2,
                const float* __restrict__ W3,
                const float* __restrict__ W4,
                float* __restrict__ out)
{
    __shared__ float sX[BT * 5];
    __shared__ int sMp;

    const int tid = threadIdx.x;
    const size_t row = (size_t)blockIdx.x * BT + tid;

    // zero-fill this block's output tile first (STGs fly early, fire-and-forget)
    {
        float4* ov = reinterpret_cast<float4*>(out + (size_t)blockIdx.x * (BT * 10));
        const float4 z = make_float4(0.f, 0.f, 0.f, 0.f);
        #pragma unroll
        for (int i = tid; i < BT * 10 / 4; i += BT) ov[i] = z;
    }

    // stage x tile: 320 coalesced LDG.128 -> STS.128
    {
        const float4* xv = reinterpret_cast<const float4*>(x) +
                           (size_t)blockIdx.x * (BT * 5 / 4);
        float4* sx4 = reinterpret_cast<float4*>(sX);
        #pragma unroll
        for (int i = tid; i < BT * 5 / 4; i += BT) sx4[i] = xv[i];
    }

    // warp 0: inline minpop from W2 (L2-resident; overlapped with staging above)
    if (tid < 32) {
        float mx = W2[tid];
        #pragma unroll
        for (int j = 1; j < 32; j++) mx = fmaxf(mx, W2[j * 32 + tid]);
        #pragma unroll
        for (int s = 16; s > 0; s >>= 1)
            mx = fmaxf(mx, __shfl_xor_sync(0xffffffffu, mx, s));
        if (tid == 0) {
            int mp = 1;  // smallest popc whose bound popc*cmax could round to >= 2
            while (mp < 33 && (float)mp * mx < 1.99f) mp++;
            sMp = mp;
        }
    }
    __syncthreads();   // sX/sMp ready; zero-fill ordered before rare scatter

    const int mp = sMp;

    // conflict-free LDS.32 (stride 5, coprime with 32 banks)
    const float x0 = sX[tid * 5 + 0];
    const float x1 = sX[tid * 5 + 1];
    const float x2 = sX[tid * 5 + 2];
    const float x3 = sX[tid * 5 + 3];
    const float x4 = sX[tid * 5 + 4];

    // Layer 1: dense 32x5, weights from __constant__ (R8-validated order)
    unsigned mask1 = 0;
    #pragma unroll
    for (int o = 0; o < 32; o++) {
        float a = cW1[o * 5 + 0] * x0;
        a = fmaf(cW1[o * 5 + 1], x1, a);
        a = fmaf(cW1[o * 5 + 2], x2, a);
        a = fmaf(cW1[o * 5 + 3], x3, a);
        a = fmaf(cW1[o * 5 + 4], x4, a);
        if (a >= 2.0f) mask1 |= 1u << o;
    }

    // gate (~1e-4 taken); rare path exact
    if (__popc(mask1) >= mp) {
        unsigned om = rare_path(mask1, W2, W3, W4);
        if (om) {
            float* o = out + row * 10;
            #pragma unroll
            for (int j = 0; j < 10; j++)
                o[j] = ((om >> j) & 1u) ? 1.0f : 0.0f;
        }
    }
}

extern "C" void kernel_launch(void* const* d_in, const int* in_sizes, int n_in,
                              void* d_out, int out_size)
{
    const float* x  = (const float*)d_in[0];
    const float* W1 = (const float*)d_in[1];
    const float* W2 = (const float*)d_in[2];
    const float* W3 = (const float*)d_in[3];
    const float* W4 = (const float*)d_in[4];
    float* out = (float*)d_out;

    const int B = in_sizes[0] / 5;        // 2097152
    const int grid = B / BT;              // 8192

    cudaMemcpyToSymbolAsync(cW1, W1, 160 * sizeof(float), 0,
                            cudaMemcpyDeviceToDevice, 0);
    snn_kernel<<<grid, BT>>>(x, W2, W3, W4, out);
}